// round 10
// baseline (speedup 1.0000x reference)
#include <cuda_runtime.h>
#include <cuda_fp16.h>
#include <cstdint>

#define Dm   64
#define Km   512
#define HWm  4096
#define DHWm (Dm * HWm)
#define NPOS 131072
#define NDOUT (NPOS * Dm)
#define NBLK 296               // 2 CTAs per SM
#define NTHR 256
#define NTILE 1024             // 131072 / 128 positions per tile
#define PITCHW 36              // A smem row pitch in words (64 fp16x2-words... 32 words + pad)

// ---- SMEM layout (bytes) ----
#define OFF_BH2  0                 // B fp16 fragment-ordered [64nt][4ks][32ln][uint2]  (65536)
#define OFF_AH   65536             // A tile z-hi fp16 pairs [128][PITCHW]              (18432)
#define OFF_AL   83968             // A tile z-lo fp16 pairs                            (18432)
#define OFF_SCC  102400            // ||ch||^2 fp32 [512]                               (2048)
#define OFF_CV   104448            // per-pos candidate vals [128][4]                   (2048)
#define OFF_CI   106496            // per-pos candidate idxs [128][4]                   (2048)
#define OFF_BI   108544            // per-pos final index [128]                         (512)
#define SMEM_TOTAL 109056

__device__ float g_partials[NBLK];

__device__ __forceinline__ void mma16816(float* d, const uint32_t* a, const uint32_t* b) {
    asm volatile(
        "mma.sync.aligned.m16n8k16.row.col.f32.f16.f16.f32 "
        "{%0,%1,%2,%3}, {%4,%5,%6,%7}, {%8,%9}, {%0,%1,%2,%3};\n"
        : "+f"(d[0]), "+f"(d[1]), "+f"(d[2]), "+f"(d[3])
        : "r"(a[0]), "r"(a[1]), "r"(a[2]), "r"(a[3]), "r"(b[0]), "r"(b[1]));
}

__device__ __forceinline__ uint32_t packh(__half a, __half b) {
    return ((uint32_t)__half_as_ushort(b) << 16) | (uint32_t)__half_as_ushort(a);
}
__device__ __forceinline__ uint32_t packh_hi(float a, float b, float* la, float* lb) {
    __half ha = __float2half_rn(a), hb = __float2half_rn(b);
    *la = a - __half2float(ha);
    *lb = b - __half2float(hb);
    return packh(ha, hb);
}
__device__ __forceinline__ uint32_t packh_v(float a, float b) {
    return packh(__float2half_rn(a), __float2half_rn(b));
}
__device__ __forceinline__ float lo_h(uint32_t w) {
    return __half2float(__ushort_as_half((unsigned short)(w & 0xFFFF)));
}
__device__ __forceinline__ float hi_h(uint32_t w) {
    return __half2float(__ushort_as_half((unsigned short)(w >> 16)));
}

// lexicographic (value, index) less: first-occurrence argmin semantics
__device__ __forceinline__ bool lexlt(float av, int ai, float bv, int bi) {
    return (av < bv) || (av == bv && ai < bi);
}
// insert (v,i) into sorted top-4 list
__device__ __forceinline__ void ins4(float* cv, int* ci, float v, int i) {
    const bool lt1 = lexlt(v, i, cv[0], ci[0]);
    const bool lt2 = lexlt(v, i, cv[1], ci[1]);
    const bool lt3 = lexlt(v, i, cv[2], ci[2]);
    const bool lt4 = lexlt(v, i, cv[3], ci[3]);
    if (lt4) { cv[3] = lt3 ? cv[2] : v; ci[3] = lt3 ? ci[2] : i; }
    if (lt3) { cv[2] = lt2 ? cv[1] : v; ci[2] = lt2 ? ci[1] : i; }
    if (lt2) { cv[1] = lt1 ? cv[0] : v; ci[1] = lt1 ? ci[0] : i; }
    if (lt1) { cv[0] = v; ci[0] = i; }
}

__global__ __launch_bounds__(NTHR, 2)
void vq_mma(const float* __restrict__ z,
            const float* __restrict__ cb,
            float* __restrict__ out) {
    extern __shared__ char smem[];
    uint2* BH2 = (uint2*)(smem + OFF_BH2);
    uint32_t* AH = (uint32_t*)(smem + OFF_AH);
    uint32_t* AL = (uint32_t*)(smem + OFF_AL);
    float* s_scc = (float*)(smem + OFF_SCC);
    float* s_cv = (float*)(smem + OFF_CV);
    int*   s_ci = (int*)  (smem + OFF_CI);
    int*   s_bi = (int*)  (smem + OFF_BI);

    const int tid = threadIdx.x, wid = tid >> 5, lid = tid & 31;
    const int g = lid >> 2, q = lid & 3;       // mma fragment coords
    const int wbase = wid * 16;                // this warp's 16 rows of the tile

    // ---- codebook -> fp16 fragment-ordered smem + rounded norms ----
    // Fragment (nt, ks, lane): code row r = nt*8+g; uint2 = dims (d0,d0+1),(d0+8,d0+9), d0=16ks+2q
    for (int j = tid; j < 64 * 4 * 32; j += NTHR) {
        const int l = j & 31, ks = (j >> 5) & 3, nt = j >> 7;
        const int gg = l >> 2, qq = l & 3;
        const int r = nt * 8 + gg;
        const int d0 = ks * 16 + qq * 2;
        const float2 c0 = *(const float2*)(cb + r * Dm + d0);
        const float2 c1 = *(const float2*)(cb + r * Dm + d0 + 8);
        BH2[j] = make_uint2(packh_v(c0.x, c0.y), packh_v(c1.x, c1.y));
    }
    // ||ch||^2 from the fp16-ROUNDED codebook (consistent with the MMA operand)
    for (int k = tid; k < Km; k += NTHR) {
        const float* row = cb + k * Dm;
        float acc = 0.f;
        #pragma unroll
        for (int d = 0; d < Dm; d++) {
            const float ch = __half2float(__float2half_rn(row[d]));
            acc = fmaf(ch, ch, acc);
        }
        s_scc[k] = acc;
    }
    __syncthreads();

    float errsum = 0.f;

    for (int t = blockIdx.x; t < NTILE; t += gridDim.x) {
        const int p0 = t << 7;
        const int b = p0 >> 12, hw0 = p0 & (HWm - 1);
        const float* zb = z + b * DHWm + hw0;

        // ---- stage A tile: z -> fp16 hi/lo smem ----
        #pragma unroll
        for (int it = 0; it < 16; it++) {
            const int i = it * NTHR + tid;
            const int ap = i & 127, dp = i >> 7;
            const float z0 = zb[(2 * dp)     * HWm + ap];
            const float z1 = zb[(2 * dp + 1) * HWm + ap];
            float la, lb;
            const uint32_t hp = packh_hi(z0, z1, &la, &lb);
            AH[ap * PITCHW + dp] = hp;
            AL[ap * PITCHW + dp] = packh_v(la, lb);
        }
        __syncthreads();

        // ---- load A fragments (resident) ----
        uint32_t aH[4][4], aL[4][4];
        {
            const int r0w = (wbase + g) * PITCHW;
            const int r1w = r0w + 8 * PITCHW;
            #pragma unroll
            for (int ks = 0; ks < 4; ks++) {
                const int o = ks * 8 + q;
                aH[ks][0] = AH[r0w + o];     aH[ks][1] = AH[r1w + o];
                aH[ks][2] = AH[r0w + o + 4]; aH[ks][3] = AH[r1w + o + 4];
                aL[ks][0] = AL[r0w + o];     aL[ks][1] = AL[r1w + o];
                aL[ks][2] = AL[r0w + o + 4]; aL[ks][3] = AL[r1w + o + 4];
            }
        }

        // ---- scan all 512 codes: 64 n-tiles; 8 HMMA each (2 chains of depth 4) ----
        float rAv1 = 3.4e38f, rAv2 = 3.4e38f, rBv1 = 3.4e38f, rBv2 = 3.4e38f;
        int   rAi1 = 0, rAi2 = 0, rBi1 = 0, rBi2 = 0;

        #pragma unroll 2
        for (int nt = 0; nt < 64; nt++) {
            float aHH[4] = {0.f, 0.f, 0.f, 0.f};
            float aLH[4] = {0.f, 0.f, 0.f, 0.f};
            const int fb = nt * 4 * 32 + lid;
            #pragma unroll
            for (int ks = 0; ks < 4; ks++) {
                const uint2 bh = BH2[fb + ks * 32];   // one LDS.64, conflict-free
                mma16816(aHH, aH[ks], (const uint32_t*)&bh);
                mma16816(aLH, aL[ks], (const uint32_t*)&bh);
            }
            const int n0 = nt * 8 + q * 2;
            const float2 sc = *(const float2*)&s_scc[n0];
            const float d00 = fmaf(-2.f, aHH[0] + aLH[0], sc.x);
            const float d01 = fmaf(-2.f, aHH[1] + aLH[1], sc.y);
            const float d10 = fmaf(-2.f, aHH[2] + aLH[2], sc.x);
            const float d11 = fmaf(-2.f, aHH[3] + aLH[3], sc.y);
            if (d00 < rAv1)      { rAv2 = rAv1; rAi2 = rAi1; rAv1 = d00; rAi1 = n0; }
            else if (d00 < rAv2) { rAv2 = d00; rAi2 = n0; }
            if (d01 < rAv1)      { rAv2 = rAv1; rAi2 = rAi1; rAv1 = d01; rAi1 = n0 + 1; }
            else if (d01 < rAv2) { rAv2 = d01; rAi2 = n0 + 1; }
            if (d10 < rBv1)      { rBv2 = rBv1; rBi2 = rBi1; rBv1 = d10; rBi1 = n0; }
            else if (d10 < rBv2) { rBv2 = d10; rBi2 = n0; }
            if (d11 < rBv1)      { rBv2 = rBv1; rBi2 = rBi1; rBv1 = d11; rBi1 = n0 + 1; }
            else if (d11 < rBv2) { rBv2 = d11; rBi2 = n0 + 1; }
        }

        // ---- merge to best-4 across the 4 lanes sharing each row ----
        float cvA[4] = {rAv1, rAv2, 3.4e38f, 3.4e38f};
        int   ciA[4] = {rAi1, rAi2, 0x7FFFFFF0, 0x7FFFFFF1};
        float cvB[4] = {rBv1, rBv2, 3.4e38f, 3.4e38f};
        int   ciB[4] = {rBi1, rBi2, 0x7FFFFFF0, 0x7FFFFFF1};
        #pragma unroll
        for (int m = 1; m <= 2; m <<= 1) {
            float ov[4]; int oi[4];
            #pragma unroll
            for (int j = 0; j < 4; j++) {
                ov[j] = __shfl_xor_sync(0xFFFFFFFFu, cvA[j], m);
                oi[j] = __shfl_xor_sync(0xFFFFFFFFu, ciA[j], m);
            }
            #pragma unroll
            for (int j = 0; j < 4; j++) ins4(cvA, ciA, ov[j], oi[j]);
            #pragma unroll
            for (int j = 0; j < 4; j++) {
                ov[j] = __shfl_xor_sync(0xFFFFFFFFu, cvB[j], m);
                oi[j] = __shfl_xor_sync(0xFFFFFFFFu, ciB[j], m);
            }
            #pragma unroll
            for (int j = 0; j < 4; j++) ins4(cvB, ciB, ov[j], oi[j]);
        }
        if (q == 0) {
            const int pA = wbase + g, pB = wbase + g + 8;
            #pragma unroll
            for (int j = 0; j < 4; j++) {
                s_cv[pA * 4 + j] = cvA[j]; s_ci[pA * 4 + j] = ciA[j];
                s_cv[pB * 4 + j] = cvB[j]; s_ci[pB * 4 + j] = ciB[j];
            }
        }
        __syncthreads();

        // ---- phase 1: decide final index (margin-gated exact fp64 refine) ----
        if (tid < 128) {
            const int pos = tid;
            const float4 cv = *(const float4*)&s_cv[pos * 4];
            const int4   ci = *(const int4*)  &s_ci[pos * 4];
            int bi = ci.x;
            if (cv.y - cv.x < 0.5f) {   // ambiguous under perturbed-codebook screen
                const float* zp = zb + pos;
                float zf[Dm];
                #pragma unroll
                for (int d = 0; d < Dm; d++) zf[d] = zp[d * HWm];
                const int cand[4] = {ci.x, ci.y, ci.z, ci.w};
                double bd = 1e300; int bidx = 0x7FFFFFFF;
                #pragma unroll
                for (int j = 0; j < 4; j++) {
                    const float* cr = cb + cand[j] * Dm;
                    double acc = 0.0;
                    #pragma unroll
                    for (int d = 0; d < Dm; d++) {
                        const double tdf = (double)zf[d] - (double)__ldg(cr + d);
                        acc = fma(tdf, tdf, acc);
                    }
                    // lexicographic (dist, idx): exact first-occurrence semantics
                    if (acc < bd || (acc == bd && cand[j] < bidx)) { bd = acc; bidx = cand[j]; }
                }
                bi = bidx;
            }
            s_bi[pos] = bi;
        }
        __syncthreads();

        // ---- phase 2: all 256 threads gather q, write, errsum ----
        {
            const int pos = tid & 127, h = tid >> 7;
            const int bi = s_bi[pos];
            const float2* qr = (const float2*)(cb + bi * Dm + h * 32);
            float* op = out + b * DHWm + hw0 + pos;
            const uint32_t* ahp = AH + pos * PITCHW + h * 16;
            const uint32_t* alp = AL + pos * PITCHW + h * 16;
            #pragma unroll
            for (int jp = 0; jp < 16; jp++) {
                const uint32_t hw_ = ahp[jp];
                const uint32_t lw_ = alp[jp];
                const float z0 = lo_h(hw_) + lo_h(lw_);   // zf reconstruct (err ~2^-22)
                const float z1 = hi_h(hw_) + hi_h(lw_);
                const float2 qv = __ldg(qr + jp);
                const int d = h * 32 + 2 * jp;
                op[d * HWm]       = qv.x;
                op[(d + 1) * HWm] = qv.y;
                const float e0 = z0 - qv.x;
                const float e1 = z1 - qv.y;
                errsum = fmaf(e0, e0, errsum);
                errsum = fmaf(e1, e1, errsum);
            }
        }
        __syncthreads();   // A tile + candidate arrays reused next iteration
    }

    // ---- deterministic block reduction of errsum ----
    __shared__ float red[NTHR];
    red[tid] = errsum;
    __syncthreads();
    #pragma unroll
    for (int off = NTHR / 2; off > 0; off >>= 1) {
        if (tid < off) red[tid] += red[tid + off];
        __syncthreads();
    }
    if (tid == 0) g_partials[blockIdx.x] = red[0];
}

__global__ void vq_loss(float* __restrict__ out, int out_size) {
    __shared__ float red[NTHR];
    const int tid = threadIdx.x;
    float v = 0.f;
    for (int i = tid; i < NBLK; i += NTHR) v += g_partials[i];
    red[tid] = v;
    __syncthreads();
    #pragma unroll
    for (int off = NTHR / 2; off > 0; off >>= 1) {
        if (tid < off) red[tid] += red[tid + off];
        __syncthreads();
    }
    const float loss = 1.25f * red[0] / (float)NDOUT;
    for (int i = NDOUT + tid; i < out_size; i += NTHR) out[i] = loss;
}

extern "C" void kernel_launch(void* const* d_in, const int* in_sizes, int n_in,
                              void* d_out, int out_size) {
    const float* z  = (const float*)d_in[0];   // [32, 64, 64, 64] fp32 NCHW
    const float* cb = (const float*)d_in[1];   // [512, 64] fp32
    float* out = (float*)d_out;

    cudaFuncSetAttribute(vq_mma, cudaFuncAttributeMaxDynamicSharedMemorySize, SMEM_TOTAL);

    vq_mma<<<NBLK, NTHR, SMEM_TOTAL>>>(z, cb, out);
    vq_loss<<<1, NTHR>>>(out, out_size);
}